// round 10
// baseline (speedup 1.0000x reference)
#include <cuda_runtime.h>
#include <cstdint>

// out[b,t,f] = relu( r2[t<16][f] + sum_c sign(x[b,t,c])*sign(w_sc[c,f]) )
//
// conv2's input is ste_sign(relu(...)) == +1 everywhere (sign(0)=+1), so the
// conv1 branch is dead and conv2+bn2 collapse to a per-f constant table (two
// variants: t<16 sees the causal zero-pad on the dilated tap). The shortcut is
// an exact +-1 binary GEMM via XOR+popcount.
//
// R10: same as R7/R9 but with the L2 eviction hints expressed via the
// createpolicy + .L2::cache_hint form (the direct .L2::evict_* modifier on
// v4.f32 is rejected by this ptxas; cache_hint supports all widths).
// x read with evict_last policy (persists across graph replays; x=134MB vs
// L2=126MB), out stored with evict_first policy (never pollutes L2).

#define EPSBN 1e-3f
#define ROWS_PER_WARP 16
#define TOTAL_ROWS (32 * 8192)   // 262144

__device__ uint4 g_wbits[128];      // f -> packed sign bits (word k bit l <-> channel 4l+k)
__device__ int   g_part[8][2][128]; // partial conv2 sign-sums per 16-channel slice

// ---------------- precompute: 12 blocks x 128 threads, float4 loads ----------------
__global__ void precompute_kernel(const float* __restrict__ w2,
                                  const float* __restrict__ w_sc) {
    int b = blockIdx.x;
    int tid = threadIdx.x;
    if (b < 4) {
        // Pack word j=b of the shortcut-weight sign bits for all 128 f.
        if (tid < 32) {
            int j = b;
            const float4* w4 = (const float4*)w_sc;
            unsigned wbit[4] = {0u, 0u, 0u, 0u};
#pragma unroll
            for (int l = 0; l < 32; ++l) {
                float4 v = w4[(4 * l + j) * 32 + tid];   // f = 4*tid .. 4*tid+3
                if (v.x >= 0.f) wbit[0] |= (1u << l);
                if (v.y >= 0.f) wbit[1] |= (1u << l);
                if (v.z >= 0.f) wbit[2] |= (1u << l);
                if (v.w >= 0.f) wbit[3] |= (1u << l);
            }
#pragma unroll
            for (int k = 0; k < 4; ++k)
                reinterpret_cast<unsigned*>(&g_wbits[4 * tid + k])[j] = wbit[k];
        }
    } else {
        // Partial conv2 sign-sums for 16-channel slice j=b-4, both taps.
        if (tid < 32) {
            int j = b - 4;
            const float4* w4 = (const float4*)w2;
            int S01[4] = {0, 0, 0, 0};
            int S1[4]  = {0, 0, 0, 0};
#pragma unroll
            for (int cc = 0; cc < 16; ++cc) {
                int c = 16 * j + cc;
                float4 a = w4[c * 32 + tid];              // tap k=0
                float4 d = w4[(128 + c) * 32 + tid];      // tap k=1 (offset 16384 floats)
                S01[0] += ((a.x >= 0.f) ? 1 : -1) + ((d.x >= 0.f) ? 1 : -1);
                S01[1] += ((a.y >= 0.f) ? 1 : -1) + ((d.y >= 0.f) ? 1 : -1);
                S01[2] += ((a.z >= 0.f) ? 1 : -1) + ((d.z >= 0.f) ? 1 : -1);
                S01[3] += ((a.w >= 0.f) ? 1 : -1) + ((d.w >= 0.f) ? 1 : -1);
                S1[0]  += (d.x >= 0.f) ? 1 : -1;
                S1[1]  += (d.y >= 0.f) ? 1 : -1;
                S1[2]  += (d.z >= 0.f) ? 1 : -1;
                S1[3]  += (d.w >= 0.f) ? 1 : -1;
            }
#pragma unroll
            for (int k = 0; k < 4; ++k) {
                g_part[j][0][4 * tid + k] = S01[k];
                g_part[j][1][4 * tid + k] = S1[k];
            }
        }
    }
}

// ---------------- policy-hinted global I/O ----------------
__device__ __forceinline__ uint64_t make_policy_evict_last() {
    uint64_t pol;
    asm("createpolicy.fractional.L2::evict_last.b64 %0, 1.0;" : "=l"(pol));
    return pol;
}
__device__ __forceinline__ uint64_t make_policy_evict_first() {
    uint64_t pol;
    asm("createpolicy.fractional.L2::evict_first.b64 %0, 1.0;" : "=l"(pol));
    return pol;
}
__device__ __forceinline__ float4 ldg_hint(const float4* p, uint64_t pol) {
    float4 v;
    asm volatile("ld.global.L2::cache_hint.v4.f32 {%0,%1,%2,%3}, [%4], %5;"
                 : "=f"(v.x), "=f"(v.y), "=f"(v.z), "=f"(v.w)
                 : "l"(p), "l"(pol) : "memory");
    return v;
}
__device__ __forceinline__ void stg_hint(float4* p, float4 v, uint64_t pol) {
    asm volatile("st.global.L2::cache_hint.v4.f32 [%0], {%1,%2,%3,%4}, %5;"
                 :: "l"(p), "f"(v.x), "f"(v.y), "f"(v.z), "f"(v.w), "l"(pol)
                 : "memory");
}

// ---------------- main kernel ----------------
__global__ void __launch_bounds__(256)
resblock_main(const float* __restrict__ x, float* __restrict__ out,
              const float* __restrict__ beta2, const float* __restrict__ mean2,
              const float* __restrict__ var2) {
    __shared__ float s_r2[2][128];   // folded bias tables (+128)

    int tid  = threadIdx.x;
    int lane = tid & 31;
    int warp = tid >> 5;

    // Startup: finalize bias tables from partials (reads ~8KB, L2-resident)
    if (tid < 128) {
        int f = tid;
        int t01 = 0, t1 = 0;
#pragma unroll
        for (int j = 0; j < 8; ++j) { t01 += g_part[j][0][f]; t1 += g_part[j][1][f]; }
        float inv = rsqrtf(var2[f] + EPSBN);
        s_r2[0][f] = fmaxf(((float)t01 - mean2[f]) * inv + beta2[f], 0.f) + 128.f;
        s_r2[1][f] = fmaxf(((float)t1  - mean2[f]) * inv + beta2[f], 0.f) + 128.f;
    }
    __syncthreads();

    uint64_t polL = make_policy_evict_last();
    uint64_t polF = make_policy_evict_first();

    // Hoist this thread's 4 output columns: weights + folded common-case bias
    uint4 wb0 = g_wbits[4 * lane + 0];
    uint4 wb1 = g_wbits[4 * lane + 1];
    uint4 wb2 = g_wbits[4 * lane + 2];
    uint4 wb3 = g_wbits[4 * lane + 3];
    float bP0 = s_r2[0][4 * lane + 0];
    float bP1 = s_r2[0][4 * lane + 1];
    float bP2 = s_r2[0][4 * lane + 2];
    float bP3 = s_r2[0][4 * lane + 3];

    const float4* __restrict__ x4 = (const float4*)x;
    float4* __restrict__ o4 = (float4*)out;

    size_t row0 = ((size_t)blockIdx.x * 8 + warp) * ROWS_PER_WARP;

#pragma unroll 8
    for (int r = 0; r < ROWS_PER_WARP; ++r) {
        size_t row = row0 + r;
        float4 v = ldg_hint(x4 + row * 32 + lane, polL);

        unsigned m0 = __ballot_sync(0xffffffffu, v.x >= 0.f);
        unsigned m1 = __ballot_sync(0xffffffffu, v.y >= 0.f);
        unsigned m2 = __ballot_sync(0xffffffffu, v.z >= 0.f);
        unsigned m3 = __ballot_sync(0xffffffffu, v.w >= 0.f);

        float p0 = bP0, p1 = bP1, p2 = bP2, p3 = bP3;
        if ((row & 8191) < 16) {               // 512 of 262144 rows
            p0 = s_r2[1][4 * lane + 0];
            p1 = s_r2[1][4 * lane + 1];
            p2 = s_r2[1][4 * lane + 2];
            p3 = s_r2[1][4 * lane + 3];
        }

        int c0 = __popc(m0 ^ wb0.x) + __popc(m1 ^ wb0.y) + __popc(m2 ^ wb0.z) + __popc(m3 ^ wb0.w);
        int c1 = __popc(m0 ^ wb1.x) + __popc(m1 ^ wb1.y) + __popc(m2 ^ wb1.z) + __popc(m3 ^ wb1.w);
        int c2 = __popc(m0 ^ wb2.x) + __popc(m1 ^ wb2.y) + __popc(m2 ^ wb2.z) + __popc(m3 ^ wb2.w);
        int c3 = __popc(m0 ^ wb3.x) + __popc(m1 ^ wb3.y) + __popc(m2 ^ wb3.z) + __popc(m3 ^ wb3.w);

        float4 o;
        o.x = fmaxf(fmaf(-2.f, (float)c0, p0), 0.f);
        o.y = fmaxf(fmaf(-2.f, (float)c1, p1), 0.f);
        o.z = fmaxf(fmaf(-2.f, (float)c2, p2), 0.f);
        o.w = fmaxf(fmaf(-2.f, (float)c3, p3), 0.f);
        stg_hint(o4 + row * 32 + lane, o, polF);
    }
}

extern "C" void kernel_launch(void* const* d_in, const int* in_sizes, int n_in,
                              void* d_out, int out_size) {
    const float* x     = (const float*)d_in[0];
    // d_in[1] = w1 (dead), d_in[4..6] = bn1 params (dead)
    const float* w2    = (const float*)d_in[2];
    const float* w_sc  = (const float*)d_in[3];
    const float* beta2 = (const float*)d_in[7];
    const float* mean2 = (const float*)d_in[8];
    const float* var2  = (const float*)d_in[9];
    float* out = (float*)d_out;

    precompute_kernel<<<12, 128>>>(w2, w_sc);
    // 262144 rows, 8 warps/block * 16 rows/warp = 128 rows/block -> grid 2048
    resblock_main<<<TOTAL_ROWS / (8 * ROWS_PER_WARP), 256>>>(x, out, beta2, mean2, var2);
}

// round 11
// speedup vs baseline: 1.2166x; 1.2166x over previous
#include <cuda_runtime.h>
#include <cstdint>

// out[b,t,f] = relu( r2[t<16][f] + sum_c sign(x[b,t,c])*sign(w_sc[c,f]) )
//
// conv2's input is ste_sign(relu(...)) == +1 everywhere (sign(0)=+1), so the
// conv1 branch is dead and conv2+bn2 collapse to a per-f constant table (two
// variants: t<16 sees the causal zero-pad on the dilated tap). The shortcut is
// an exact +-1 binary GEMM via XOR+popcount.
//
// R11: R10 minus the L2 eviction hints (measured conclusively negative:
// x=134MB > L2=126MB thrashes the evict_last set; main 42->55us). Plain
// float4 I/O, 12-block vectorized precompute, bias finalize folded into
// main-kernel startup (2 launches total).

#define EPSBN 1e-3f
#define ROWS_PER_WARP 16
#define TOTAL_ROWS (32 * 8192)   // 262144

__device__ uint4 g_wbits[128];      // f -> packed sign bits (word k bit l <-> channel 4l+k)
__device__ int   g_part[8][2][128]; // partial conv2 sign-sums per 16-channel slice

// ---------------- precompute: 12 blocks x 128 threads, float4 loads ----------------
__global__ void precompute_kernel(const float* __restrict__ w2,
                                  const float* __restrict__ w_sc) {
    int b = blockIdx.x;
    int tid = threadIdx.x;
    if (b < 4) {
        // Pack word j=b of the shortcut-weight sign bits for all 128 f.
        if (tid < 32) {
            int j = b;
            const float4* w4 = (const float4*)w_sc;
            unsigned wbit[4] = {0u, 0u, 0u, 0u};
#pragma unroll
            for (int l = 0; l < 32; ++l) {
                float4 v = w4[(4 * l + j) * 32 + tid];   // f = 4*tid .. 4*tid+3
                if (v.x >= 0.f) wbit[0] |= (1u << l);
                if (v.y >= 0.f) wbit[1] |= (1u << l);
                if (v.z >= 0.f) wbit[2] |= (1u << l);
                if (v.w >= 0.f) wbit[3] |= (1u << l);
            }
#pragma unroll
            for (int k = 0; k < 4; ++k)
                reinterpret_cast<unsigned*>(&g_wbits[4 * tid + k])[j] = wbit[k];
        }
    } else {
        // Partial conv2 sign-sums for 16-channel slice j=b-4, both taps.
        if (tid < 32) {
            int j = b - 4;
            const float4* w4 = (const float4*)w2;
            int S01[4] = {0, 0, 0, 0};
            int S1[4]  = {0, 0, 0, 0};
#pragma unroll
            for (int cc = 0; cc < 16; ++cc) {
                int c = 16 * j + cc;
                float4 a = w4[c * 32 + tid];              // tap k=0
                float4 d = w4[(128 + c) * 32 + tid];      // tap k=1 (offset 16384 floats)
                S01[0] += ((a.x >= 0.f) ? 1 : -1) + ((d.x >= 0.f) ? 1 : -1);
                S01[1] += ((a.y >= 0.f) ? 1 : -1) + ((d.y >= 0.f) ? 1 : -1);
                S01[2] += ((a.z >= 0.f) ? 1 : -1) + ((d.z >= 0.f) ? 1 : -1);
                S01[3] += ((a.w >= 0.f) ? 1 : -1) + ((d.w >= 0.f) ? 1 : -1);
                S1[0]  += (d.x >= 0.f) ? 1 : -1;
                S1[1]  += (d.y >= 0.f) ? 1 : -1;
                S1[2]  += (d.z >= 0.f) ? 1 : -1;
                S1[3]  += (d.w >= 0.f) ? 1 : -1;
            }
#pragma unroll
            for (int k = 0; k < 4; ++k) {
                g_part[j][0][4 * tid + k] = S01[k];
                g_part[j][1][4 * tid + k] = S1[k];
            }
        }
    }
}

// ---------------- main kernel ----------------
__global__ void __launch_bounds__(256)
resblock_main(const float* __restrict__ x, float* __restrict__ out,
              const float* __restrict__ beta2, const float* __restrict__ mean2,
              const float* __restrict__ var2) {
    __shared__ float s_r2[2][128];   // folded bias tables (+128)

    int tid  = threadIdx.x;
    int lane = tid & 31;
    int warp = tid >> 5;

    // Startup: finalize bias tables from partials (reads ~8KB, L2-resident)
    if (tid < 128) {
        int f = tid;
        int t01 = 0, t1 = 0;
#pragma unroll
        for (int j = 0; j < 8; ++j) { t01 += g_part[j][0][f]; t1 += g_part[j][1][f]; }
        float inv = rsqrtf(var2[f] + EPSBN);
        s_r2[0][f] = fmaxf(((float)t01 - mean2[f]) * inv + beta2[f], 0.f) + 128.f;
        s_r2[1][f] = fmaxf(((float)t1  - mean2[f]) * inv + beta2[f], 0.f) + 128.f;
    }
    __syncthreads();

    // Hoist this thread's 4 output columns: weights + folded common-case bias
    uint4 wb0 = g_wbits[4 * lane + 0];
    uint4 wb1 = g_wbits[4 * lane + 1];
    uint4 wb2 = g_wbits[4 * lane + 2];
    uint4 wb3 = g_wbits[4 * lane + 3];
    float bP0 = s_r2[0][4 * lane + 0];
    float bP1 = s_r2[0][4 * lane + 1];
    float bP2 = s_r2[0][4 * lane + 2];
    float bP3 = s_r2[0][4 * lane + 3];

    const float4* __restrict__ x4 = (const float4*)x;
    float4* __restrict__ o4 = (float4*)out;

    size_t row0 = ((size_t)blockIdx.x * 8 + warp) * ROWS_PER_WARP;

#pragma unroll 8
    for (int r = 0; r < ROWS_PER_WARP; ++r) {
        size_t row = row0 + r;
        float4 v = x4[row * 32 + lane];

        unsigned m0 = __ballot_sync(0xffffffffu, v.x >= 0.f);
        unsigned m1 = __ballot_sync(0xffffffffu, v.y >= 0.f);
        unsigned m2 = __ballot_sync(0xffffffffu, v.z >= 0.f);
        unsigned m3 = __ballot_sync(0xffffffffu, v.w >= 0.f);

        float p0 = bP0, p1 = bP1, p2 = bP2, p3 = bP3;
        if ((row & 8191) < 16) {               // 512 of 262144 rows
            p0 = s_r2[1][4 * lane + 0];
            p1 = s_r2[1][4 * lane + 1];
            p2 = s_r2[1][4 * lane + 2];
            p3 = s_r2[1][4 * lane + 3];
        }

        int c0 = __popc(m0 ^ wb0.x) + __popc(m1 ^ wb0.y) + __popc(m2 ^ wb0.z) + __popc(m3 ^ wb0.w);
        int c1 = __popc(m0 ^ wb1.x) + __popc(m1 ^ wb1.y) + __popc(m2 ^ wb1.z) + __popc(m3 ^ wb1.w);
        int c2 = __popc(m0 ^ wb2.x) + __popc(m1 ^ wb2.y) + __popc(m2 ^ wb2.z) + __popc(m3 ^ wb2.w);
        int c3 = __popc(m0 ^ wb3.x) + __popc(m1 ^ wb3.y) + __popc(m2 ^ wb3.z) + __popc(m3 ^ wb3.w);

        float4 o;
        o.x = fmaxf(fmaf(-2.f, (float)c0, p0), 0.f);
        o.y = fmaxf(fmaf(-2.f, (float)c1, p1), 0.f);
        o.z = fmaxf(fmaf(-2.f, (float)c2, p2), 0.f);
        o.w = fmaxf(fmaf(-2.f, (float)c3, p3), 0.f);
        o4[row * 32 + lane] = o;
    }
}

extern "C" void kernel_launch(void* const* d_in, const int* in_sizes, int n_in,
                              void* d_out, int out_size) {
    const float* x     = (const float*)d_in[0];
    // d_in[1] = w1 (dead), d_in[4..6] = bn1 params (dead)
    const float* w2    = (const float*)d_in[2];
    const float* w_sc  = (const float*)d_in[3];
    const float* beta2 = (const float*)d_in[7];
    const float* mean2 = (const float*)d_in[8];
    const float* var2  = (const float*)d_in[9];
    float* out = (float*)d_out;

    precompute_kernel<<<12, 128>>>(w2, w_sc);
    // 262144 rows, 8 warps/block * 16 rows/warp = 128 rows/block -> grid 2048
    resblock_main<<<TOTAL_ROWS / (8 * ROWS_PER_WARP), 256>>>(x, out, beta2, mean2, var2);
}

// round 12
// speedup vs baseline: 1.2685x; 1.0426x over previous
#include <cuda_runtime.h>
#include <cstdint>

// out[b,t,f] = relu( r2[t<16][f] + sum_c sign(x[b,t,c])*sign(w_sc[c,f]) )
//
// conv2's input is ste_sign(relu(...)) == +1 everywhere (sign(0)=+1), so the
// conv1 branch is dead and conv2+bn2 collapse to a per-f constant table (two
// variants: t<16 sees the causal zero-pad on the dilated tap). The shortcut is
// an exact +-1 binary GEMM via XOR+popcount.
//
// R12 = best measured pieces assembled:
//  - main: R6's warp-private cp.async pipeline (fastest measured, 42.2us),
//    tables read from global per-warp, no startup finalize.
//  - precompute1: 12 blocks x 128 ACTIVE threads (4x the parallelism of the
//    4.7us R5 version), fully coalesced.
//  - precompute2: tiny 1-block finalize, biases pre-folded (+128).

#define EPSBN 1e-3f
#define NSTAGE 3
#define SROWS 4                        // rows per stage per warp
#define WARP_ROWS 32                   // rows per warp
#define SITER (WARP_ROWS / SROWS)      // 8 stage-iterations
#define ROWS_PER_BLOCK (8 * WARP_ROWS) // 256
#define TOTAL_ROWS (32 * 8192)         // 262144

__device__ uint4 g_wbits[128];      // f -> packed sign bits (word k bit l <-> channel 4l+k)
__device__ float g_r2[2][128];      // folded (+128) bias tables: [0]=t>=16, [1]=t<16
__device__ int   g_part[8][2][128]; // partial conv2 sign-sums per 16-channel slice

// ---------------- precompute1: 12 blocks x 128 threads, all active ----------------
__global__ void precompute1(const float* __restrict__ w2,
                            const float* __restrict__ w_sc) {
    int f = threadIdx.x;    // 0..127
    int b = blockIdx.x;
    if (b < 4) {
        // Pack word j=b of shortcut-weight sign bits for output column f.
        // Loads are coalesced across f (512B per warp-instruction), 32 independent.
        int j = b;
        unsigned w = 0u;
#pragma unroll
        for (int l = 0; l < 32; ++l) {
            if (w_sc[(4 * l + j) * 128 + f] >= 0.f) w |= (1u << l);
        }
        reinterpret_cast<unsigned*>(&g_wbits[f])[j] = w;
    } else {
        // Partial conv2 sign-sums for 16-channel slice j=b-4, both taps.
        int j = b - 4;
        int S01 = 0, S1 = 0;
#pragma unroll
        for (int cc = 0; cc < 16; ++cc) {
            int c = 16 * j + cc;
            float a  = w2[c * 128 + f];           // tap k=0
            float bb = w2[16384 + c * 128 + f];   // tap k=1
            S01 += ((a >= 0.f) ? 1 : -1) + ((bb >= 0.f) ? 1 : -1);
            S1  += ((bb >= 0.f) ? 1 : -1);
        }
        g_part[j][0][f] = S01;
        g_part[j][1][f] = S1;
    }
}

// ---------------- precompute2: finalize folded bias tables ----------------
__global__ void precompute2(const float* __restrict__ beta2,
                            const float* __restrict__ mean2,
                            const float* __restrict__ var2) {
    int f = threadIdx.x;
    int t01 = 0, t1 = 0;
#pragma unroll
    for (int j = 0; j < 8; ++j) { t01 += g_part[j][0][f]; t1 += g_part[j][1][f]; }
    float inv = rsqrtf(var2[f] + EPSBN);
    g_r2[0][f] = fmaxf(((float)t01 - mean2[f]) * inv + beta2[f], 0.f) + 128.f;
    g_r2[1][f] = fmaxf(((float)t1  - mean2[f]) * inv + beta2[f], 0.f) + 128.f;
}

// ---------------- cp.async helpers ----------------
__device__ __forceinline__ void cp_async16(uint32_t smem_addr, const void* gptr) {
    asm volatile("cp.async.cg.shared.global [%0], [%1], 16;\n"
                 :: "r"(smem_addr), "l"(gptr));
}
__device__ __forceinline__ void cp_commit() {
    asm volatile("cp.async.commit_group;\n" ::: "memory");
}
template <int N>
__device__ __forceinline__ void cp_wait() {
    asm volatile("cp.async.wait_group %0;\n" :: "n"(N) : "memory");
}

// ---------------- main kernel: warp-private pipeline, no barriers ----------------
__global__ void __launch_bounds__(256, 4)
resblock_main(const float* __restrict__ x, float* __restrict__ out) {
    // [warp][stage][row][lane] float4 : 8*3*4*32*16 = 48 KB
    __shared__ float4 s_x[8][NSTAGE][SROWS * 32];

    int tid  = threadIdx.x;
    int lane = tid & 31;
    int warp = tid >> 5;

    // Hoist this thread's 4 output columns: weights + folded bias (+128 already)
    uint4 wb0 = g_wbits[4 * lane + 0];
    uint4 wb1 = g_wbits[4 * lane + 1];
    uint4 wb2 = g_wbits[4 * lane + 2];
    uint4 wb3 = g_wbits[4 * lane + 3];
    float bP0 = g_r2[0][4 * lane + 0];
    float bP1 = g_r2[0][4 * lane + 1];
    float bP2 = g_r2[0][4 * lane + 2];
    float bP3 = g_r2[0][4 * lane + 3];

    size_t warp_row0 = (size_t)blockIdx.x * ROWS_PER_BLOCK + (size_t)warp * WARP_ROWS;
    const float4* __restrict__ gx = (const float4*)x + warp_row0 * 32 + lane;
    float4* __restrict__ o4 = (float4*)out;

    uint32_t sbase = (uint32_t)__cvta_generic_to_shared(&s_x[warp][0][0]);

    // prologue: issue stages 0 and 1 (each thread copies ONLY what it reads back)
#pragma unroll
    for (int s = 0; s < 2; ++s) {
#pragma unroll
        for (int r = 0; r < SROWS; ++r) {
            cp_async16(sbase + (uint32_t)((s * SROWS + r) * 32 + lane) * 16,
                       gx + (size_t)(s * SROWS + r) * 32);
        }
        cp_commit();
    }

#pragma unroll
    for (int s = 0; s < SITER; ++s) {
        if (s + 2 < SITER) {
            int ps = s + 2, b = ps % NSTAGE;
#pragma unroll
            for (int r = 0; r < SROWS; ++r) {
                cp_async16(sbase + (uint32_t)((b * SROWS + r) * 32 + lane) * 16,
                           gx + (size_t)(ps * SROWS + r) * 32);
            }
            cp_commit();
            cp_wait<2>();
        } else if (s == SITER - 2) {
            cp_wait<1>();
        } else {
            cp_wait<0>();
        }

        const float4* buf = s_x[warp][s % NSTAGE];
#pragma unroll
        for (int r = 0; r < SROWS; ++r) {
            float4 v = buf[r * 32 + lane];   // this thread's own cp.async result

            unsigned m0 = __ballot_sync(0xffffffffu, v.x >= 0.f);
            unsigned m1 = __ballot_sync(0xffffffffu, v.y >= 0.f);
            unsigned m2 = __ballot_sync(0xffffffffu, v.z >= 0.f);
            unsigned m3 = __ballot_sync(0xffffffffu, v.w >= 0.f);

            size_t row = warp_row0 + (size_t)(s * SROWS + r);

            float p0 = bP0, p1 = bP1, p2 = bP2, p3 = bP3;
            if ((row & 8191) < 16) {               // 512 of 262144 rows
                p0 = g_r2[1][4 * lane + 0];
                p1 = g_r2[1][4 * lane + 1];
                p2 = g_r2[1][4 * lane + 2];
                p3 = g_r2[1][4 * lane + 3];
            }

            int c0 = __popc(m0 ^ wb0.x) + __popc(m1 ^ wb0.y) + __popc(m2 ^ wb0.z) + __popc(m3 ^ wb0.w);
            int c1 = __popc(m0 ^ wb1.x) + __popc(m1 ^ wb1.y) + __popc(m2 ^ wb1.z) + __popc(m3 ^ wb1.w);
            int c2 = __popc(m0 ^ wb2.x) + __popc(m1 ^ wb2.y) + __popc(m2 ^ wb2.z) + __popc(m3 ^ wb2.w);
            int c3 = __popc(m0 ^ wb3.x) + __popc(m1 ^ wb3.y) + __popc(m2 ^ wb3.z) + __popc(m3 ^ wb3.w);

            float4 o;
            o.x = fmaxf(fmaf(-2.f, (float)c0, p0), 0.f);
            o.y = fmaxf(fmaf(-2.f, (float)c1, p1), 0.f);
            o.z = fmaxf(fmaf(-2.f, (float)c2, p2), 0.f);
            o.w = fmaxf(fmaf(-2.f, (float)c3, p3), 0.f);
            o4[row * 32 + lane] = o;
        }
    }
}

extern "C" void kernel_launch(void* const* d_in, const int* in_sizes, int n_in,
                              void* d_out, int out_size) {
    const float* x     = (const float*)d_in[0];
    // d_in[1] = w1 (dead), d_in[4..6] = bn1 params (dead)
    const float* w2    = (const float*)d_in[2];
    const float* w_sc  = (const float*)d_in[3];
    const float* beta2 = (const float*)d_in[7];
    const float* mean2 = (const float*)d_in[8];
    const float* var2  = (const float*)d_in[9];
    float* out = (float*)d_out;

    precompute1<<<12, 128>>>(w2, w_sc);
    precompute2<<<1, 128>>>(beta2, mean2, var2);
    resblock_main<<<TOTAL_ROWS / ROWS_PER_BLOCK, 256>>>(x, out);
}